// round 13
// baseline (speedup 1.0000x reference)
#include <cuda_runtime.h>
#include <cuda_fp16.h>
#include <cstdint>

// Problem constants (Head_84533546320520)
#define BATCH 8
#define SEQ   2048
#define DEMB  1024
#define HEAD  64
#define NROWS (BATCH * SEQ)   // 16384
#define SCALE 0.125f          // HEAD^-0.5

// fp16 scratch: projected q (pre-scaled), k, v
__device__ __half g_qh[NROWS * HEAD];
__device__ __half g_kh[NROWS * HEAD];
__device__ __half g_vh[NROWS * HEAD];

// Pre-converted weights (single fp16)
__device__ __half g_wh[3][DEMB * HEAD];

// ===========================================================================
// helpers
// ===========================================================================
__device__ __forceinline__ uint32_t smem_to_u32(const void* p) {
    uint32_t a;
    asm("{ .reg .u64 t; cvta.to.shared.u64 t, %1; cvt.u32.u64 %0, t; }"
        : "=r"(a) : "l"(p));
    return a;
}
__device__ __forceinline__ void ldsm_x4(uint32_t* r, uint32_t addr) {
    asm volatile("ldmatrix.sync.aligned.m8n8.x4.shared.b16 {%0,%1,%2,%3}, [%4];"
        : "=r"(r[0]), "=r"(r[1]), "=r"(r[2]), "=r"(r[3]) : "r"(addr));
}
__device__ __forceinline__ void ldsm_x4_trans(uint32_t* r, uint32_t addr) {
    asm volatile("ldmatrix.sync.aligned.m8n8.x4.trans.shared.b16 {%0,%1,%2,%3}, [%4];"
        : "=r"(r[0]), "=r"(r[1]), "=r"(r[2]), "=r"(r[3]) : "r"(addr));
}
__device__ __forceinline__ void mma_f16(float* d, const uint32_t* a, const uint32_t* b) {
    asm volatile(
        "mma.sync.aligned.m16n8k16.row.col.f32.f16.f16.f32 "
        "{%0,%1,%2,%3}, {%4,%5,%6,%7}, {%8,%9}, {%0,%1,%2,%3};"
        : "+f"(d[0]), "+f"(d[1]), "+f"(d[2]), "+f"(d[3])
        : "r"(a[0]), "r"(a[1]), "r"(a[2]), "r"(a[3]), "r"(b[0]), "r"(b[1]));
}
__device__ __forceinline__ uint32_t cvt2h(float x, float y) {
    __half2 hb = __float22half2_rn(make_float2(x, y));
    return *reinterpret_cast<uint32_t*>(&hb);
}
__device__ __forceinline__ void cp_async16(uint32_t saddr, const void* gaddr) {
    asm volatile("cp.async.cg.shared.global [%0], [%1], 16;"
        :: "r"(saddr), "l"(gaddr) : "memory");
}
#define CP_COMMIT()  asm volatile("cp.async.commit_group;" ::: "memory")
#define CP_WAIT(n)   asm volatile("cp.async.wait_group %0;" :: "n"(n) : "memory")

// ===========================================================================
// Kernel 0: convert W to fp16. grid (64, 3), block 256.
// ===========================================================================
__global__ __launch_bounds__(256) void wsplit_kernel(
    const float* __restrict__ Wq, const float* __restrict__ Wk,
    const float* __restrict__ Wv)
{
    const int which = blockIdx.y;
    const float* __restrict__ W = (which == 0) ? Wq : (which == 1) ? Wk : Wv;
    int idx = blockIdx.x * 256 + threadIdx.x;
    float4 t = reinterpret_cast<const float4*>(W)[idx];
    *reinterpret_cast<uint2*>(&g_wh[which][idx * 4]) =
        make_uint2(cvt2h(t.x, t.y), cvt2h(t.z, t.w));
}

// ===========================================================================
// Kernel 1: projections, single-term fp16, CHUNK-PAIR structure:
// one __syncthreads per 128 K-columns (8 syncs total, was 16).
// Quad-buffered A and B tiles. grid = (NROWS/128, 3), block = 256.
// ===========================================================================
#define KC 64
#define NPAIR 8                   // 16 chunks as 8 pairs
#define APAD 72
#define ABUF (128 * APAD * 2)     // 18432 B
#define BBUF (64 * APAD * 2)      // 9216 B
#define PROJ_SMEM (4 * ABUF + 4 * BBUF)   // 110592 B

__global__ __launch_bounds__(256) void proj_mma_kernel(
    const float* __restrict__ q, const float* __restrict__ k,
    const float* __restrict__ v)
{
    extern __shared__ __align__(16) char smc[];
    const uint32_t base = smem_to_u32(smc);
    const uint32_t bBase = base + 4 * ABUF;

    const int which = blockIdx.y;
    const float* __restrict__ X = (which == 0) ? q : (which == 1) ? k : v;
    const __half* __restrict__ Wh = g_wh[which];
    const float postmul = (which == 0) ? SCALE : 1.0f;

    const int tid = threadIdx.x;
    const int wid = tid >> 5;
    const int lane = tid & 31;
    const int l16 = lane & 15;
    const int hi8 = (lane >> 4) << 3;
    const int row0 = blockIdx.x * 128;
    const int m0 = wid * 16;

    // fp16 A data for one chunk-pair, held in registers (2 chunks x 8 uint2)
    uint2 hA[2][8];

    auto ldcvt = [&](int c0) {
        #pragma unroll
        for (int j = 0; j < 2; j++) {
            const int k0 = (c0 + j) * KC;
            float4 t[8];
            #pragma unroll
            for (int i = 0; i < 8; i++) {
                int idx = tid + i * 256;
                int r = idx >> 4, cg = idx & 15;
                t[i] = *reinterpret_cast<const float4*>(
                    X + (size_t)(row0 + r) * DEMB + k0 + cg * 4);
            }
            #pragma unroll
            for (int i = 0; i < 8; i++) {
                hA[j][i].x = cvt2h(t[i].x, t[i].y);
                hA[j][i].y = cvt2h(t[i].z, t[i].w);
            }
        }
    };
    auto storeA = [&](int s) {
        #pragma unroll
        for (int j = 0; j < 2; j++) {
            const uint32_t aB = base + (s * 2 + j) * ABUF;
            #pragma unroll
            for (int i = 0; i < 8; i++) {
                int idx = tid + i * 256;
                int r = idx >> 4, cg = idx & 15;
                uint32_t off = (uint32_t)(r * APAD + cg * 4) * 2;
                asm volatile("st.shared.v2.b32 [%0], {%1, %2};"
                    :: "r"(aB + off), "r"(hA[j][i].x), "r"(hA[j][i].y) : "memory");
            }
        }
    };
    auto cpB = [&](int c0, int s) {
        #pragma unroll
        for (int j = 0; j < 2; j++) {
            const uint32_t bB = bBase + (s * 2 + j) * BBUF;
            const int k0 = (c0 + j) * KC;
            #pragma unroll
            for (int i = 0; i < 2; i++) {
                int rem = tid + i * 256;       // 0..511
                int r = rem >> 3, cq = rem & 7;
                cp_async16(bB + r * 144 + cq * 16,
                           Wh + (size_t)(k0 + r) * HEAD + cq * 8);
            }
        }
        CP_COMMIT();
    };

    float acc[8][4] = {};

    ldcvt(0);
    cpB(0, 0);

    for (int p = 0; p < NPAIR; p++) {
        const int s = p & 1;
        storeA(s);
        CP_WAIT(0);            // B(pair p) arrived
        __syncthreads();       // A(pair p) stores visible; MMA(p-1) drained
        if (p + 1 < NPAIR) {
            ldcvt((p + 1) * 2);          // LDG overlaps MMA below
            cpB((p + 1) * 2, s ^ 1);
        }

        #pragma unroll
        for (int j = 0; j < 2; j++) {
            const uint32_t aB = base + (s * 2 + j) * ABUF;
            const uint32_t bB = bBase + (s * 2 + j) * BBUF;
            #pragma unroll
            for (int kk = 0; kk < 4; kk++) {
                uint32_t af[4];
                uint32_t aoff = (uint32_t)(((m0 + l16) * APAD + kk * 16 + hi8) * 2);
                ldsm_x4(af, aB + aoff);
                #pragma unroll
                for (int nb = 0; nb < 4; nb++) {
                    uint32_t bh[4];
                    uint32_t boff = (uint32_t)(((kk * 16 + l16) * APAD + nb * 16 + hi8) * 2);
                    ldsm_x4_trans(bh, bB + boff);
                    mma_f16(acc[2 * nb + 0], af, bh + 0);
                    mma_f16(acc[2 * nb + 1], af, bh + 2);
                }
            }
        }
    }

    const int r = lane >> 2;
    const int cc = (lane & 3) * 2;
    const size_t rA = (size_t)(row0 + m0 + r) * HEAD;
    const size_t rB = (size_t)(row0 + m0 + r + 8) * HEAD;
    __half* outH = (which == 0) ? g_qh : (which == 1) ? g_kh : g_vh;
    #pragma unroll
    for (int j = 0; j < 8; j++) {
        *reinterpret_cast<uint32_t*>(&outH[rA + j * 8 + cc]) =
            cvt2h(acc[j][0] * postmul, acc[j][1] * postmul);
        *reinterpret_cast<uint32_t*>(&outH[rB + j * 8 + cc]) =
            cvt2h(acc[j][2] * postmul, acc[j][3] * postmul);
    }
}

// ===========================================================================
// Kernel 2: flash attention, 128-wide key tiles (UNCHANGED from R12 win).
// grid = (SEQ/64, BATCH), block = 128. Single-term fp16, fp32 accum.
// ===========================================================================
#define AP 72
#define BUF2 (128 * AP * 2)           // 18432 B per K or V tile
#define STAGE2 (2 * BUF2)             // 36864 B
#define ATTN_SMEM (2 * STAGE2 + 512)  // 74240 B
#define NT2 (SEQ / 128)               // 16

__global__ __launch_bounds__(128) void attn_mma_kernel(
    const int* __restrict__ mask, float* __restrict__ out)
{
    extern __shared__ __align__(16) char smc[];
    const uint32_t smemB = smem_to_u32(smc);
    float* biasS = reinterpret_cast<float*>(smc + 2 * STAGE2);

    const int b  = blockIdx.y;
    const int q0 = blockIdx.x * 64;
    const size_t base = (size_t)b * SEQ * HEAD;

    const int tid  = threadIdx.x;
    const int wid  = tid >> 5;
    const int lane = tid & 31;
    const int l16  = lane & 15;
    const int hi8  = (lane >> 4) << 3;
    const int m0   = wid * 16;
    const int c2   = (lane & 3) * 2;

    const int krow = (lane & 7) + ((lane & 16) >> 1);
    const int hcol = (lane & 8);

    #pragma unroll
    for (int i = 0; i < 4; i++) {
        int idx = tid + i * 128;
        int r = idx >> 3, cq = idx & 7;
        uint4 th = *reinterpret_cast<const uint4*>(g_qh + base + (size_t)(q0 + r) * HEAD + cq * 8);
        *reinterpret_cast<uint4*>(smc + r * 144 + cq * 16) = th;
    }
    __syncthreads();
    uint32_t qh[4][4];
    #pragma unroll
    for (int kh = 0; kh < 4; kh++) {
        uint32_t aoff = (uint32_t)(((m0 + l16) * AP + kh * 16 + hi8) * 2);
        ldsm_x4(qh[kh], smemB + aoff);
    }
    __syncthreads();

    const __half* srcs[2] = {g_kh + base, g_vh + base};
    {
        #pragma unroll
        for (int i = 0; i < 16; i++) {
            const int buf = i >> 3;
            int rem = tid + (i & 7) * 128;
            int r = rem >> 3, cq = rem & 7;
            cp_async16(smemB + buf * BUF2 + r * 144 + cq * 16,
                       srcs[buf] + (size_t)r * HEAD + cq * 8);
        }
        CP_COMMIT();
    }

    const float NEG_INF = __int_as_float(0xff800000);
    float mR0 = NEG_INF, mR1 = NEG_INF, lS0 = 0.f, lS1 = 0.f;
    float o[8][4] = {};

    for (int kt = 0; kt < NT2; kt++) {
        const int s = kt & 1;
        const uint32_t stB = smemB + s * STAGE2;

        if (kt + 1 < NT2) {
            const int k1 = (kt + 1) * 128;
            const uint32_t st2 = smemB + ((kt + 1) & 1) * STAGE2;
            #pragma unroll
            for (int i = 0; i < 16; i++) {
                const int buf = i >> 3;
                int rem = tid + (i & 7) * 128;
                int r = rem >> 3, cq = rem & 7;
                cp_async16(st2 + buf * BUF2 + r * 144 + cq * 16,
                           srcs[buf] + (size_t)(k1 + r) * HEAD + cq * 8);
            }
            CP_COMMIT();
            CP_WAIT(1);
        } else {
            CP_WAIT(0);
        }
        biasS[tid] = (mask[(size_t)b * SEQ + kt * 128 + tid] != 0) ? 0.f : -1e30f;
        __syncthreads();

        float sF[16][4] = {};
        #pragma unroll
        for (int kh = 0; kh < 4; kh++) {
            #pragma unroll
            for (int nb = 0; nb < 8; nb++) {
                uint32_t bh[4];
                uint32_t boff = (uint32_t)(((nb * 16 + krow) * AP + kh * 16 + hcol) * 2);
                ldsm_x4(bh, stB + boff);
                mma_f16(sF[2 * nb],     qh[kh], bh);
                mma_f16(sF[2 * nb + 1], qh[kh], bh + 2);
            }
        }

        float mx0 = NEG_INF, mx1 = NEG_INF;
        #pragma unroll
        for (int j = 0; j < 16; j++) {
            float2 bv = *reinterpret_cast<float2*>(&biasS[j * 8 + c2]);
            sF[j][0] += bv.x; sF[j][1] += bv.y; sF[j][2] += bv.x; sF[j][3] += bv.y;
            mx0 = fmaxf(mx0, fmaxf(sF[j][0], sF[j][1]));
            mx1 = fmaxf(mx1, fmaxf(sF[j][2], sF[j][3]));
        }
        mx0 = fmaxf(mx0, __shfl_xor_sync(0xffffffffu, mx0, 1));
        mx0 = fmaxf(mx0, __shfl_xor_sync(0xffffffffu, mx0, 2));
        mx1 = fmaxf(mx1, __shfl_xor_sync(0xffffffffu, mx1, 1));
        mx1 = fmaxf(mx1, __shfl_xor_sync(0xffffffffu, mx1, 2));
        float mn0 = fmaxf(mR0, mx0), mn1 = fmaxf(mR1, mx1);
        float a0 = __expf(mR0 - mn0), a1 = __expf(mR1 - mn1);
        float sm0 = 0.f, sm1 = 0.f;
        #pragma unroll
        for (int j = 0; j < 16; j++) {
            sF[j][0] = __expf(sF[j][0] - mn0);
            sF[j][1] = __expf(sF[j][1] - mn0);
            sF[j][2] = __expf(sF[j][2] - mn1);
            sF[j][3] = __expf(sF[j][3] - mn1);
            sm0 += sF[j][0] + sF[j][1];
            sm1 += sF[j][2] + sF[j][3];
        }
        sm0 += __shfl_xor_sync(0xffffffffu, sm0, 1);
        sm0 += __shfl_xor_sync(0xffffffffu, sm0, 2);
        sm1 += __shfl_xor_sync(0xffffffffu, sm1, 1);
        sm1 += __shfl_xor_sync(0xffffffffu, sm1, 2);
        lS0 = lS0 * a0 + sm0; lS1 = lS1 * a1 + sm1;
        mR0 = mn0; mR1 = mn1;
        #pragma unroll
        for (int j = 0; j < 8; j++) {
            o[j][0] *= a0; o[j][1] *= a0; o[j][2] *= a1; o[j][3] *= a1;
        }

        #pragma unroll
        for (int kb = 0; kb < 8; kb++) {
            uint32_t ah[4];
            ah[0] = cvt2h(sF[2 * kb][0],     sF[2 * kb][1]);
            ah[1] = cvt2h(sF[2 * kb][2],     sF[2 * kb][3]);
            ah[2] = cvt2h(sF[2 * kb + 1][0], sF[2 * kb + 1][1]);
            ah[3] = cvt2h(sF[2 * kb + 1][2], sF[2 * kb + 1][3]);
            #pragma unroll
            for (int nb = 0; nb < 4; nb++) {
                uint32_t vh[4];
                uint32_t boff = (uint32_t)(((kb * 16 + l16) * AP + nb * 16 + hi8) * 2);
                ldsm_x4_trans(vh, stB + BUF2 + boff);
                mma_f16(o[2 * nb],     ah, vh);
                mma_f16(o[2 * nb + 1], ah, vh + 2);
            }
        }
        __syncthreads();
    }

    float inv0 = 1.f / lS0, inv1 = 1.f / lS1;
    int rowA = b * SEQ + q0 + m0 + (lane >> 2);
    #pragma unroll
    for (int j = 0; j < 8; j++) {
        *reinterpret_cast<float2*>(out + (size_t)rowA * HEAD + j * 8 + c2) =
            make_float2(o[j][0] * inv0, o[j][1] * inv0);
        *reinterpret_cast<float2*>(out + (size_t)(rowA + 8) * HEAD + j * 8 + c2) =
            make_float2(o[j][2] * inv1, o[j][3] * inv1);
    }
}

// ---------------------------------------------------------------------------
extern "C" void kernel_launch(void* const* d_in, const int* in_sizes, int n_in,
                              void* d_out, int out_size)
{
    const void* big[3]   = {0, 0, 0};
    const void* small[3] = {0, 0, 0};
    const void* mk = 0;
    int nb = 0, ns = 0;
    for (int i = 0; i < n_in; i++) {
        if (in_sizes[i] == NROWS * DEMB)      { if (nb < 3) big[nb++] = d_in[i]; }
        else if (in_sizes[i] == DEMB * HEAD)  { if (ns < 3) small[ns++] = d_in[i]; }
        else if (in_sizes[i] == BATCH * SEQ)  { mk = d_in[i]; }
    }
    const float* q  = (const float*)big[0];
    const float* k  = (const float*)big[1];
    const float* v  = (const float*)big[2];
    const float* Wq = (const float*)small[0];
    const float* Wk = (const float*)small[1];
    const float* Wv = (const float*)small[2];
    const int*   mask = (const int*)mk;
    float* out = (float*)d_out;

    static bool attr_set = false;
    if (!attr_set) {
        cudaFuncSetAttribute(proj_mma_kernel, cudaFuncAttributeMaxDynamicSharedMemorySize, PROJ_SMEM);
        cudaFuncSetAttribute(attn_mma_kernel, cudaFuncAttributeMaxDynamicSharedMemorySize, ATTN_SMEM);
        attr_set = true;
    }

    wsplit_kernel<<<dim3(64, 3), 256>>>(Wq, Wk, Wv);
    proj_mma_kernel<<<dim3(NROWS / 128, 3), 256, PROJ_SMEM>>>(q, k, v);
    attn_mma_kernel<<<dim3(SEQ / 64, BATCH), 128, ATTN_SMEM>>>(mask, out);
}

// round 14
// speedup vs baseline: 1.1708x; 1.1708x over previous
#include <cuda_runtime.h>
#include <cuda_fp16.h>
#include <cstdint>

// Problem constants (Head_84533546320520)
#define BATCH 8
#define SEQ   2048
#define DEMB  1024
#define HEAD  64
#define NROWS (BATCH * SEQ)   // 16384
#define SCALE 0.125f          // HEAD^-0.5
#define LOG2E 1.4426950408889634f

// fp16 scratch: projected q (pre-scaled by SCALE*log2e), k, v
__device__ __half g_qh[NROWS * HEAD];
__device__ __half g_kh[NROWS * HEAD];
__device__ __half g_vh[NROWS * HEAD];

// Pre-converted weights (single fp16)
__device__ __half g_wh[3][DEMB * HEAD];

// ===========================================================================
// helpers
// ===========================================================================
__device__ __forceinline__ uint32_t smem_to_u32(const void* p) {
    uint32_t a;
    asm("{ .reg .u64 t; cvta.to.shared.u64 t, %1; cvt.u32.u64 %0, t; }"
        : "=r"(a) : "l"(p));
    return a;
}
__device__ __forceinline__ void ldsm_x4(uint32_t* r, uint32_t addr) {
    asm volatile("ldmatrix.sync.aligned.m8n8.x4.shared.b16 {%0,%1,%2,%3}, [%4];"
        : "=r"(r[0]), "=r"(r[1]), "=r"(r[2]), "=r"(r[3]) : "r"(addr));
}
__device__ __forceinline__ void ldsm_x4_trans(uint32_t* r, uint32_t addr) {
    asm volatile("ldmatrix.sync.aligned.m8n8.x4.trans.shared.b16 {%0,%1,%2,%3}, [%4];"
        : "=r"(r[0]), "=r"(r[1]), "=r"(r[2]), "=r"(r[3]) : "r"(addr));
}
__device__ __forceinline__ void mma_f16(float* d, const uint32_t* a, const uint32_t* b) {
    asm volatile(
        "mma.sync.aligned.m16n8k16.row.col.f32.f16.f16.f32 "
        "{%0,%1,%2,%3}, {%4,%5,%6,%7}, {%8,%9}, {%0,%1,%2,%3};"
        : "+f"(d[0]), "+f"(d[1]), "+f"(d[2]), "+f"(d[3])
        : "r"(a[0]), "r"(a[1]), "r"(a[2]), "r"(a[3]), "r"(b[0]), "r"(b[1]));
}
__device__ __forceinline__ uint32_t cvt2h(float x, float y) {
    __half2 hb = __float22half2_rn(make_float2(x, y));
    return *reinterpret_cast<uint32_t*>(&hb);
}
__device__ __forceinline__ void cp_async16(uint32_t saddr, const void* gaddr) {
    asm volatile("cp.async.cg.shared.global [%0], [%1], 16;"
        :: "r"(saddr), "l"(gaddr) : "memory");
}
#define CP_COMMIT()  asm volatile("cp.async.commit_group;" ::: "memory")
#define CP_WAIT(n)   asm volatile("cp.async.wait_group %0;" :: "n"(n) : "memory")

// ===========================================================================
// Kernel 0: convert W to fp16. grid (64, 3), block 256.
// ===========================================================================
__global__ __launch_bounds__(256) void wsplit_kernel(
    const float* __restrict__ Wq, const float* __restrict__ Wk,
    const float* __restrict__ Wv)
{
    const int which = blockIdx.y;
    const float* __restrict__ W = (which == 0) ? Wq : (which == 1) ? Wk : Wv;
    int idx = blockIdx.x * 256 + threadIdx.x;
    float4 t = reinterpret_cast<const float4*>(W)[idx];
    *reinterpret_cast<uint2*>(&g_wh[which][idx * 4]) =
        make_uint2(cvt2h(t.x, t.y), cvt2h(t.z, t.w));
}

// ===========================================================================
// Kernel 1: projections (R12-exact, single-term fp16, double-buffered).
// q epilogue pre-scales by SCALE*LOG2E for the exp2 softmax.
// grid = (NROWS/128, 3), block = 256.
// ===========================================================================
#define KC 64
#define NCH (DEMB / KC)
#define APAD 72
#define ABUF (128 * APAD * 2)
#define BBUF (64 * APAD * 2)
#define PROJ_SMEM (2 * ABUF + 2 * BBUF)   // 55296 B

__global__ __launch_bounds__(256) void proj_mma_kernel(
    const float* __restrict__ q, const float* __restrict__ k,
    const float* __restrict__ v)
{
    extern __shared__ __align__(16) char smc[];
    const uint32_t base = smem_to_u32(smc);
    const uint32_t bBase = base + 2 * ABUF;

    const int which = blockIdx.y;
    const float* __restrict__ X = (which == 0) ? q : (which == 1) ? k : v;
    const __half* __restrict__ Wh = g_wh[which];
    const float postmul = (which == 0) ? (SCALE * LOG2E) : 1.0f;

    const int tid = threadIdx.x;
    const int wid = tid >> 5;
    const int lane = tid & 31;
    const int l16 = lane & 15;
    const int hi8 = (lane >> 4) << 3;
    const int row0 = blockIdx.x * 128;
    const int m0 = wid * 16;

    float4 aR8[8];
    auto loadA = [&](int k0) {
        #pragma unroll
        for (int i = 0; i < 8; i++) {
            int idx = tid + i * 256;
            int r = idx >> 4, cg = idx & 15;
            aR8[i] = *reinterpret_cast<const float4*>(
                X + (size_t)(row0 + r) * DEMB + k0 + cg * 4);
        }
    };
    auto convA = [&](int s) {
        const uint32_t aB = base + s * ABUF;
        #pragma unroll
        for (int i = 0; i < 8; i++) {
            int idx = tid + i * 256;
            int r = idx >> 4, cg = idx & 15;
            float4 t = aR8[i];
            uint32_t h0 = cvt2h(t.x, t.y);
            uint32_t h1 = cvt2h(t.z, t.w);
            uint32_t off = (uint32_t)(r * APAD + cg * 4) * 2;
            asm volatile("st.shared.v2.b32 [%0], {%1, %2};" :: "r"(aB + off), "r"(h0), "r"(h1) : "memory");
        }
    };
    auto cpB = [&](int c, int s) {
        const uint32_t bHi = bBase + s * BBUF;
        const int k0 = c * KC;
        #pragma unroll
        for (int i = 0; i < 2; i++) {
            int rem = tid + i * 256;
            int r = rem >> 3, cq = rem & 7;
            cp_async16(bHi + r * 144 + cq * 16,
                       Wh + (size_t)(k0 + r) * HEAD + cq * 8);
        }
        CP_COMMIT();
    };

    float acc[8][4] = {};

    loadA(0);
    cpB(0, 0);

    for (int c = 0; c < NCH; c++) {
        const int s = c & 1;
        convA(s);
        if (c + 1 < NCH) loadA((c + 1) * KC);
        CP_WAIT(0);
        __syncthreads();
        if (c + 1 < NCH) cpB(c + 1, s ^ 1);

        const uint32_t aB  = base + s * ABUF;
        const uint32_t bHi = bBase + s * BBUF;
        #pragma unroll
        for (int kk = 0; kk < 4; kk++) {
            uint32_t af[4];
            uint32_t aoff = (uint32_t)(((m0 + l16) * APAD + kk * 16 + hi8) * 2);
            ldsm_x4(af, aB + aoff);
            #pragma unroll
            for (int nb = 0; nb < 4; nb++) {
                uint32_t bh[4];
                uint32_t boff = (uint32_t)(((kk * 16 + l16) * APAD + nb * 16 + hi8) * 2);
                ldsm_x4_trans(bh, bHi + boff);
                mma_f16(acc[2 * nb + 0], af, bh + 0);
                mma_f16(acc[2 * nb + 1], af, bh + 2);
            }
        }
    }

    const int r = lane >> 2;
    const int cc = (lane & 3) * 2;
    const size_t rA = (size_t)(row0 + m0 + r) * HEAD;
    const size_t rB = (size_t)(row0 + m0 + r + 8) * HEAD;
    __half* outH = (which == 0) ? g_qh : (which == 1) ? g_kh : g_vh;
    #pragma unroll
    for (int j = 0; j < 8; j++) {
        *reinterpret_cast<uint32_t*>(&outH[rA + j * 8 + cc]) =
            cvt2h(acc[j][0] * postmul, acc[j][1] * postmul);
        *reinterpret_cast<uint32_t*>(&outH[rB + j * 8 + cc]) =
            cvt2h(acc[j][2] * postmul, acc[j][3] * postmul);
    }
}

// ===========================================================================
// Kernel 2: flash attention, 128-wide key tiles, 3-stage smem ring,
// PV pipelined one round behind S (overlaps softmax MUFU with PV tensor),
// exp2-domain softmax (q pre-scaled by log2e).
// grid = (SEQ/64, BATCH), block = 128.
// ===========================================================================
#define AP 72
#define BUF2 (128 * AP * 2)           // 18432 B per K or V tile
#define STAGE2 (2 * BUF2)             // 36864 B (K then V)
#define NST 3
#define ATTN_SMEM (NST * STAGE2 + 512)  // 111104 B
#define NT2 (SEQ / 128)               // 16

__global__ __launch_bounds__(128) void attn_mma_kernel(
    const int* __restrict__ mask, float* __restrict__ out)
{
    extern __shared__ __align__(16) char smc[];
    const uint32_t smemB = smem_to_u32(smc);
    float* biasS = reinterpret_cast<float*>(smc + NST * STAGE2);

    const int b  = blockIdx.y;
    const int q0 = blockIdx.x * 64;
    const size_t base = (size_t)b * SEQ * HEAD;

    const int tid  = threadIdx.x;
    const int wid  = tid >> 5;
    const int lane = tid & 31;
    const int l16  = lane & 15;
    const int hi8  = (lane >> 4) << 3;
    const int m0   = wid * 16;
    const int c2   = (lane & 3) * 2;

    const int krow = (lane & 7) + ((lane & 16) >> 1);
    const int hcol = (lane & 8);

    // stage Q (fits inside stage-0 region; consumed before prefetch(0))
    #pragma unroll
    for (int i = 0; i < 4; i++) {
        int idx = tid + i * 128;
        int r = idx >> 3, cq = idx & 7;
        uint4 th = *reinterpret_cast<const uint4*>(g_qh + base + (size_t)(q0 + r) * HEAD + cq * 8);
        *reinterpret_cast<uint4*>(smc + r * 144 + cq * 16) = th;
    }
    __syncthreads();
    uint32_t qh[4][4];
    #pragma unroll
    for (int kh = 0; kh < 4; kh++) {
        uint32_t aoff = (uint32_t)(((m0 + l16) * AP + kh * 16 + hi8) * 2);
        ldsm_x4(qh[kh], smemB + aoff);
    }
    __syncthreads();   // Q frags extracted before prefetch(0) overwrites stage 0

    const __half* srcs[2] = {g_kh + base, g_vh + base};
    auto prefetch = [&](int t) {
        const uint32_t st = smemB + (t % NST) * STAGE2;
        const int k0 = t * 128;
        #pragma unroll
        for (int i = 0; i < 16; i++) {
            const int buf = i >> 3;
            int rem = tid + (i & 7) * 128;      // 0..1023
            int r = rem >> 3, cq = rem & 7;
            cp_async16(st + buf * BUF2 + r * 144 + cq * 16,
                       srcs[buf] + (size_t)(k0 + r) * HEAD + cq * 8);
        }
        CP_COMMIT();
    };

    prefetch(0);

    const float NEG_INF = __int_as_float(0xff800000);
    float mR0 = NEG_INF, mR1 = NEG_INF, lS0 = 0.f, lS1 = 0.f;
    float o[8][4] = {};
    uint32_t pPrev[8][4];     // P(t-1) as packed fp16 A-frags

    for (int kt = 0; kt < NT2; kt++) {
        const uint32_t stK = smemB + (kt % NST) * STAGE2;

        CP_WAIT(0);           // tile kt resident
        biasS[tid] = (mask[(size_t)b * SEQ + kt * 128 + tid] != 0) ? 0.f : -1e30f;
        __syncthreads();      // tile kt + bias visible; stage (kt+1)%NST fully drained
        if (kt + 1 < NT2) prefetch(kt + 1);   // overlaps this round's compute

        // ---- S(t) = Qh @ Kh^T over 128 keys ----
        float sF[16][4] = {};
        #pragma unroll
        for (int kh = 0; kh < 4; kh++) {
            #pragma unroll
            for (int nb = 0; nb < 8; nb++) {
                uint32_t bh[4];
                uint32_t boff = (uint32_t)(((nb * 16 + krow) * AP + kh * 16 + hcol) * 2);
                ldsm_x4(bh, stK + boff);
                mma_f16(sF[2 * nb],     qh[kh], bh);
                mma_f16(sF[2 * nb + 1], qh[kh], bh + 2);
            }
        }

        // ---- PV(t-1): tensor pipe busy while softmax below runs on MUFU/ALU ----
        if (kt > 0) {
            const uint32_t stVp = smemB + ((kt - 1) % NST) * STAGE2 + BUF2;
            #pragma unroll
            for (int kb = 0; kb < 8; kb++) {
                #pragma unroll
                for (int nb = 0; nb < 4; nb++) {
                    uint32_t vh[4];
                    uint32_t boff = (uint32_t)(((kb * 16 + l16) * AP + nb * 16 + hi8) * 2);
                    ldsm_x4_trans(vh, stVp + boff);
                    mma_f16(o[2 * nb],     pPrev[kb], vh);
                    mma_f16(o[2 * nb + 1], pPrev[kb], vh + 2);
                }
            }
        }

        // ---- softmax(t) in exp2 domain ----
        float mx0 = NEG_INF, mx1 = NEG_INF;
        #pragma unroll
        for (int j = 0; j < 16; j++) {
            float2 bv = *reinterpret_cast<float2*>(&biasS[j * 8 + c2]);
            sF[j][0] += bv.x; sF[j][1] += bv.y; sF[j][2] += bv.x; sF[j][3] += bv.y;
            mx0 = fmaxf(mx0, fmaxf(sF[j][0], sF[j][1]));
            mx1 = fmaxf(mx1, fmaxf(sF[j][2], sF[j][3]));
        }
        mx0 = fmaxf(mx0, __shfl_xor_sync(0xffffffffu, mx0, 1));
        mx0 = fmaxf(mx0, __shfl_xor_sync(0xffffffffu, mx0, 2));
        mx1 = fmaxf(mx1, __shfl_xor_sync(0xffffffffu, mx1, 1));
        mx1 = fmaxf(mx1, __shfl_xor_sync(0xffffffffu, mx1, 2));
        float mn0 = fmaxf(mR0, mx0), mn1 = fmaxf(mR1, mx1);
        float a0 = exp2f(mR0 - mn0), a1 = exp2f(mR1 - mn1);
        float sm0 = 0.f, sm1 = 0.f;
        #pragma unroll
        for (int j = 0; j < 16; j++) {
            sF[j][0] = exp2f(sF[j][0] - mn0);
            sF[j][1] = exp2f(sF[j][1] - mn0);
            sF[j][2] = exp2f(sF[j][2] - mn1);
            sF[j][3] = exp2f(sF[j][3] - mn1);
            sm0 += sF[j][0] + sF[j][1];
            sm1 += sF[j][2] + sF[j][3];
        }
        sm0 += __shfl_xor_sync(0xffffffffu, sm0, 1);
        sm0 += __shfl_xor_sync(0xffffffffu, sm0, 2);
        sm1 += __shfl_xor_sync(0xffffffffu, sm1, 1);
        sm1 += __shfl_xor_sync(0xffffffffu, sm1, 2);
        lS0 = lS0 * a0 + sm0; lS1 = lS1 * a1 + sm1;
        mR0 = mn0; mR1 = mn1;
        // rescale o AFTER PV(t-1) accumulated (reads o -> waits on those MMAs)
        #pragma unroll
        for (int j = 0; j < 8; j++) {
            o[j][0] *= a0; o[j][1] *= a0; o[j][2] *= a1; o[j][3] *= a1;
        }

        // ---- pack P(t) for next round's PV ----
        #pragma unroll
        for (int kb = 0; kb < 8; kb++) {
            pPrev[kb][0] = cvt2h(sF[2 * kb][0],     sF[2 * kb][1]);
            pPrev[kb][1] = cvt2h(sF[2 * kb][2],     sF[2 * kb][3]);
            pPrev[kb][2] = cvt2h(sF[2 * kb + 1][0], sF[2 * kb + 1][1]);
            pPrev[kb][3] = cvt2h(sF[2 * kb + 1][2], sF[2 * kb + 1][3]);
        }
        __syncthreads();   // all warps done reading stage kt before it is refilled
    }

    // ---- final PV flush for tile NT2-1 ----
    {
        const uint32_t stVp = smemB + ((NT2 - 1) % NST) * STAGE2 + BUF2;
        #pragma unroll
        for (int kb = 0; kb < 8; kb++) {
            #pragma unroll
            for (int nb = 0; nb < 4; nb++) {
                uint32_t vh[4];
                uint32_t boff = (uint32_t)(((kb * 16 + l16) * AP + nb * 16 + hi8) * 2);
                ldsm_x4_trans(vh, stVp + boff);
                mma_f16(o[2 * nb],     pPrev[kb], vh);
                mma_f16(o[2 * nb + 1], pPrev[kb], vh + 2);
            }
        }
    }

    float inv0 = 1.f / lS0, inv1 = 1.f / lS1;
    int rowA = b * SEQ + q0 + m0 + (lane >> 2);
    #pragma unroll
    for (int j = 0; j < 8; j++) {
        *reinterpret_cast<float2*>(out + (size_t)rowA * HEAD + j * 8 + c2) =
            make_float2(o[j][0] * inv0, o[j][1] * inv0);
        *reinterpret_cast<float2*>(out + (size_t)(rowA + 8) * HEAD + j * 8 + c2) =
            make_float2(o[j][2] * inv1, o[j][3] * inv1);
    }
}

// ---------------------------------------------------------------------------
extern "C" void kernel_launch(void* const* d_in, const int* in_sizes, int n_in,
                              void* d_out, int out_size)
{
    const void* big[3]   = {0, 0, 0};
    const void* small[3] = {0, 0, 0};
    const void* mk = 0;
    int nb = 0, ns = 0;
    for (int i = 0; i < n_in; i++) {
        if (in_sizes[i] == NROWS * DEMB)      { if (nb < 3) big[nb++] = d_in[i]; }
        else if (in_sizes[i] == DEMB * HEAD)  { if (ns < 3) small[ns++] = d_in[i]; }
        else if (in_sizes[i] == BATCH * SEQ)  { mk = d_in[i]; }
    }
    const float* q  = (const float*)big[0];
    const float* k  = (const float*)big[1];
    const float* v  = (const float*)big[2];
    const float* Wq = (const float*)small[0];
    const float* Wk = (const float*)small[1];
    const float* Wv = (const float*)small[2];
    const int*   mask = (const int*)mk;
    float* out = (float*)d_out;

    static bool attr_set = false;
    if (!attr_set) {
        cudaFuncSetAttribute(proj_mma_kernel, cudaFuncAttributeMaxDynamicSharedMemorySize, PROJ_SMEM);
        cudaFuncSetAttribute(attn_mma_kernel, cudaFuncAttributeMaxDynamicSharedMemorySize, ATTN_SMEM);
        attr_set = true;
    }

    wsplit_kernel<<<dim3(64, 3), 256>>>(Wq, Wk, Wv);
    proj_mma_kernel<<<dim3(NROWS / 128, 3), 256, PROJ_SMEM>>>(q, k, v);
    attn_mma_kernel<<<dim3(SEQ / 64, BATCH), 128, ATTN_SMEM>>>(mask, out);
}